// round 11
// baseline (speedup 1.0000x reference)
#include <cuda_runtime.h>
#include <math.h>
#include <stdint.h>

#define HH 16
#define BB 8
#define SS 1024
#define DMOD 1024
#define DH 64
#define NQKV 3072   // 16 heads * (64+64+64)

// ---------------- scratch (device globals; no allocation allowed) ----------------
__device__ uint32_t g_W[NQKV * DMOD];       // tf32 bits, n-major [n][k]
__device__ uint32_t g_Wo[DMOD * DMOD];      // tf32 bits, n-major [n][k]
__device__ uint32_t g_Atf[SS * BB * DMOD];  // tf32 bits of input Q, [m][k]
__device__ float g_bias[NQKV];
__device__ float g_q[HH * BB * SS * DH];    // tf32-valued floats [h][b][s][c]
__device__ float g_k[HH * BB * SS * DH];
__device__ float g_v[HH * BB * SS * DH];
__device__ float g_ctx[SS * BB * DMOD];     // tf32-valued floats [s][b][h*64+v]

// ---------------- helpers ----------------
__device__ __forceinline__ uint32_t f2tf32(float x) {
    uint32_t u;
    asm("cvt.rna.tf32.f32 %0, %1;" : "=r"(u) : "f"(x));
    return u;
}

__device__ __forceinline__ uint32_t smem_u32(const void* p) {
    uint32_t a;
    asm("{ .reg .u64 t; cvta.to.shared.u64 t, %1; cvt.u32.u64 %0, t; }"
        : "=r"(a) : "l"(p));
    return a;
}

__device__ __forceinline__ void cp16(uint32_t dst, const void* src) {
    asm volatile("cp.async.cg.shared.global [%0], [%1], 16;"
                 :: "r"(dst), "l"(src) : "memory");
}
#define CP_COMMIT() asm volatile("cp.async.commit_group;" ::: "memory")
#define CP_WAIT(n)  asm volatile("cp.async.wait_group %0;" :: "n"(n) : "memory")

__device__ __forceinline__ void mma_tf32(float* d, const uint32_t* a,
                                         uint32_t b0, uint32_t b1) {
    asm volatile(
        "mma.sync.aligned.m16n8k8.row.col.f32.tf32.tf32.f32 "
        "{%0,%1,%2,%3}, {%4,%5,%6,%7}, {%8,%9}, {%0,%1,%2,%3};"
        : "+f"(d[0]), "+f"(d[1]), "+f"(d[2]), "+f"(d[3])
        : "r"(a[0]), "r"(a[1]), "r"(a[2]), "r"(a[3]), "r"(b0), "r"(b1));
}

__device__ __forceinline__ void ldsm4(uint32_t* r, uint32_t addr) {
    asm volatile("ldmatrix.sync.aligned.m8n8.x4.shared.b16 {%0,%1,%2,%3}, [%4];"
                 : "=r"(r[0]), "=r"(r[1]), "=r"(r[2]), "=r"(r[3])
                 : "r"(addr));
}

// ---------------- pre-conversion kernels ----------------
__global__ void pack_qkv(const float* __restrict__ Wq, const float* __restrict__ bq,
                         const float* __restrict__ Wk, const float* __restrict__ bk,
                         const float* __restrict__ Wv, const float* __restrict__ bv)
{
    int idx = blockIdx.x * blockDim.x + threadIdx.x;
    if (idx >= NQKV * DMOD) return;
    int n = idx >> 10, d = idx & 1023;       // n-major [n][k]
    int h = n / 192, j = n % 192, t = j >> 6, c = j & 63;
    const float* Wsrc = (t == 0) ? Wq : (t == 1) ? Wk : Wv;
    g_W[idx] = f2tf32(Wsrc[(h * DMOD + d) * DH + c]);
    if (idx < NQKV) {
        int nn = idx;
        int h2 = nn / 192, j2 = nn % 192, t2 = j2 >> 6, c2 = j2 & 63;
        const float* bsrc = (t2 == 0) ? bq : (t2 == 1) ? bk : bv;
        g_bias[nn] = bsrc[h2 * DH + c2];
    }
}

__global__ void pack_wo(const float* __restrict__ Wo)
{
    int idx = blockIdx.x * blockDim.x + threadIdx.x;
    if (idx >= DMOD * DMOD) return;
    int k = idx >> 10, n = idx & 1023;       // coalesced read
    g_Wo[n * DMOD + k] = f2tf32(Wo[idx]);    // n-major write
}

__global__ void cvt_q(const float* __restrict__ Q)
{
    int idx = blockIdx.x * blockDim.x + threadIdx.x;   // float4 granularity
    float4 v = *(const float4*)(Q + idx * 4);
    uint4 u = {f2tf32(v.x), f2tf32(v.y), f2tf32(v.z), f2tf32(v.w)};
    *(uint4*)(g_Atf + idx * 4) = u;
}

// ---------------- TF32 tensor-core GEMM: cp.async + ldmatrix ----------------
// Block tile 128x128x32; 8 warps (2x4), warp tile 64x32 via 4x4 m16n8k8.
// A smem [m][BK] stride 36; B smem [n][BK] stride 36 (both ldmatrix-fed).
#define BM 128
#define BN 128
#define BK 32
#define STAGES 3
#define LSTRIDE 36
#define A_WORDS (BM * LSTRIDE)              // 4608
#define B_WORDS (BN * LSTRIDE)              // 4608
#define STG_WORDS (A_WORDS + B_WORDS)       // 9216
#define GEMM_SMEM (STAGES * STG_WORDS * 4)  // 110592 B

template <int MODE>
__global__ void __launch_bounds__(256, 2) tf32_gemm(const float* __restrict__ biasparam,
                                                    float* __restrict__ C)
{
    constexpr int N = (MODE == 1) ? NQKV : DMOD;
    constexpr int K = DMOD;
    extern __shared__ uint32_t smem[];

    const uint32_t* Ag = (MODE == 1) ? g_Atf : (const uint32_t*)g_ctx;
    const uint32_t* Bg = (MODE == 1) ? g_W   : g_Wo;

    int tid = threadIdx.x;
    int warp = tid >> 5, lane = tid & 31;
    int wm = warp >> 2, wn = warp & 3;
    int g = lane >> 2, tg = lane & 3;
    int rowBase = blockIdx.y * BM;
    int colBase = blockIdx.x * BN;

    uint32_t sbase = smem_u32(smem);

    // ldmatrix per-lane byte offsets
    // A x4 tiles: (m0-7,klo)(m8-15,klo)(m0-7,khi)(m8-15,khi)
    uint32_t aoff = ((((lane >> 3) & 1) * 8 + (lane & 7)) * LSTRIDE + (lane >> 4) * 4) * 4;
    // B x4 tiles: (n0-7,klo)(n0-7,khi)(n8-15,klo)(n8-15,khi)
    uint32_t boff = (((lane >> 4) * 8 + (lane & 7)) * LSTRIDE + ((lane >> 3) & 1) * 4) * 4;

    float acc[4][4][4];
#pragma unroll
    for (int mi = 0; mi < 4; mi++)
#pragma unroll
        for (int ni = 0; ni < 4; ni++)
#pragma unroll
            for (int r = 0; r < 4; r++) acc[mi][ni][r] = 0.f;

    const int ntiles = K / BK;   // 32

    auto load_stage = [&](int kt) {
        int st = kt % STAGES;
        uint32_t sa = sbase + st * STG_WORDS * 4;
        uint32_t sb = sa + A_WORDS * 4;
        int k0 = kt * BK;
#pragma unroll
        for (int i = 0; i < 4; i++) {
            int c = tid + 256 * i;
            int row = c >> 3, seg = c & 7;
            cp16(sa + (row * LSTRIDE + seg * 4) * 4,
                 Ag + (size_t)(rowBase + row) * K + k0 + seg * 4);
        }
#pragma unroll
        for (int i = 0; i < 4; i++) {
            int c = tid + 256 * i;
            int row = c >> 3, seg = c & 7;
            cp16(sb + (row * LSTRIDE + seg * 4) * 4,
                 Bg + (size_t)(colBase + row) * K + k0 + seg * 4);
        }
        CP_COMMIT();
    };

#pragma unroll
    for (int kt = 0; kt < STAGES - 1; kt++) load_stage(kt);

    for (int kt = 0; kt < ntiles; kt++) {
        CP_WAIT(STAGES - 2);
        __syncthreads();
        if (kt + STAGES - 1 < ntiles) load_stage(kt + STAGES - 1);
        else CP_COMMIT();

        int st = kt % STAGES;
        uint32_t asu = sbase + st * STG_WORDS * 4;
        uint32_t bsu = asu + A_WORDS * 4;

#pragma unroll
        for (int ks = 0; ks < 4; ks++) {
            uint32_t afrag[4][4], bfrag[4][2];
#pragma unroll
            for (int mi = 0; mi < 4; mi++)
                ldsm4(afrag[mi],
                      asu + (((wm * 64 + mi * 16) * LSTRIDE + ks * 8) * 4) + aoff);
#pragma unroll
            for (int np = 0; np < 2; np++) {
                uint32_t tmp[4];
                ldsm4(tmp, bsu + (((wn * 32 + np * 16) * LSTRIDE + ks * 8) * 4) + boff);
                bfrag[2 * np + 0][0] = tmp[0];
                bfrag[2 * np + 0][1] = tmp[1];
                bfrag[2 * np + 1][0] = tmp[2];
                bfrag[2 * np + 1][1] = tmp[3];
            }
#pragma unroll
            for (int mi = 0; mi < 4; mi++)
#pragma unroll
                for (int ni = 0; ni < 4; ni++)
                    mma_tf32(acc[mi][ni], afrag[mi], bfrag[ni][0], bfrag[ni][1]);
        }
    }

    // epilogue
#pragma unroll
    for (int mi = 0; mi < 4; mi++) {
#pragma unroll
        for (int ni = 0; ni < 4; ni++) {
            int r0 = rowBase + wm * 64 + mi * 16 + g;
            int cn = colBase + wn * 32 + ni * 8 + tg * 2;
            if (MODE == 0) {
                float2 bv = *(const float2*)&biasparam[cn];
                float2 o0 = {acc[mi][ni][0] + bv.x, acc[mi][ni][1] + bv.y};
                float2 o1 = {acc[mi][ni][2] + bv.x, acc[mi][ni][3] + bv.y};
                *(float2*)&C[(size_t)r0 * N + cn] = o0;
                *(float2*)&C[(size_t)(r0 + 8) * N + cn] = o1;
            } else {
#pragma unroll
                for (int e = 0; e < 4; e++) {
                    int r = r0 + (e >> 1) * 8;
                    int n = cn + (e & 1);
                    int s = r >> 3, b = r & 7;
                    int h = n / 192, jj = n % 192, ty = jj >> 6, c = jj & 63;
                    float val = acc[mi][ni][e] + g_bias[n];
                    float* bufp = (ty == 0) ? g_q : (ty == 1) ? g_k : g_v;
                    bufp[((h * BB + b) * SS + s) * DH + c] =
                        __uint_as_float(f2tf32(val));   // store tf32 bits
                }
            }
        }
    }
}

// ---------------- TF32 mma.sync flash attention (unchanged) ----------------
#define KSTRIDE 68
#define VSTRIDE 72
#define PSTRIDE 68

__global__ void __launch_bounds__(256) flash_tf32()
{
    extern __shared__ uint32_t sm[];
    uint32_t* Ks = sm;
    uint32_t* Vs = Ks + 64 * KSTRIDE;
    uint32_t* Ps = Vs + 64 * VSTRIDE;

    int tid = threadIdx.x;
    int warp = tid >> 5, lane = tid & 31;
    int g = lane >> 2, tg = lane & 3;
    int qx = blockIdx.x;
    int hb = blockIdx.y;
    int h = hb >> 3, b = hb & 7;
    int qs0 = qx * 128;
    int wr = warp * 16;

    const float* qg  = g_q + ((size_t)(h * BB + b) * SS + qs0) * DH;
    const uint32_t* kg0 = (const uint32_t*)g_k + (size_t)(h * BB + b) * SS * DH;
    const uint32_t* vg0 = (const uint32_t*)g_v + (size_t)(h * BB + b) * SS * DH;

    uint32_t aq[8][4];
#pragma unroll
    for (int ki = 0; ki < 8; ki++) {
        const float* qp = qg + (wr + g) * DH + ki * 8 + tg;
        aq[ki][0] = __float_as_uint(qp[0] * 0.125f);
        aq[ki][1] = __float_as_uint(qp[8 * DH] * 0.125f);
        aq[ki][2] = __float_as_uint(qp[4] * 0.125f);
        aq[ki][3] = __float_as_uint(qp[8 * DH + 4] * 0.125f);
    }

    float o[8][4];
#pragma unroll
    for (int ni = 0; ni < 8; ni++)
#pragma unroll
        for (int e = 0; e < 4; e++) o[ni][e] = 0.f;
    float m_lo = -INFINITY, m_hi = -INFINITY, l_lo = 0.f, l_hi = 0.f;

    const int nkt = 2 * (qx + 1);
    for (int kt = 0; kt < nkt; kt++) {
        const uint32_t* kg = kg0 + (size_t)kt * 64 * DH;
        const uint32_t* vg = vg0 + (size_t)kt * 64 * DH;
        __syncthreads();
#pragma unroll
        for (int t = 0; t < 4; t++) {
            int f = tid + t * 256;
            int row = f >> 4, c4 = (f & 15) << 2;
            uint4 kv = *(const uint4*)(kg + row * DH + c4);
            uint32_t* kp = Ks + row * KSTRIDE + c4;
            kp[0] = kv.x; kp[1] = kv.y; kp[2] = kv.z; kp[3] = kv.w;
            uint4 vv = *(const uint4*)(vg + row * DH + c4);
            uint32_t* vp = Vs + row * VSTRIDE + c4;
            vp[0] = vv.x; vp[1] = vv.y; vp[2] = vv.z; vp[3] = vv.w;
        }
        __syncthreads();

        float sc[8][4];
#pragma unroll
        for (int ni = 0; ni < 8; ni++)
#pragma unroll
            for (int e = 0; e < 4; e++) sc[ni][e] = 0.f;
#pragma unroll
        for (int ki = 0; ki < 8; ki++) {
#pragma unroll
            for (int ni = 0; ni < 8; ni++) {
                const uint32_t* kb = Ks + (ni * 8 + g) * KSTRIDE + ki * 8 + tg;
                mma_tf32(sc[ni], aq[ki], kb[0], kb[4]);
            }
        }

        if (kt * 64 + 63 > qs0 + wr) {
            int rlo = qs0 + wr + g, rhi = rlo + 8;
#pragma unroll
            for (int ni = 0; ni < 8; ni++) {
                int col = kt * 64 + ni * 8 + 2 * tg;
                if (col     > rlo) sc[ni][0] = -1e30f;
                if (col + 1 > rlo) sc[ni][1] = -1e30f;
                if (col     > rhi) sc[ni][2] = -1e30f;
                if (col + 1 > rhi) sc[ni][3] = -1e30f;
            }
        }

        float mx_lo = -1e30f, mx_hi = -1e30f;
#pragma unroll
        for (int ni = 0; ni < 8; ni++) {
            mx_lo = fmaxf(mx_lo, fmaxf(sc[ni][0], sc[ni][1]));
            mx_hi = fmaxf(mx_hi, fmaxf(sc[ni][2], sc[ni][3]));
        }
        mx_lo = fmaxf(mx_lo, __shfl_xor_sync(0xffffffffu, mx_lo, 1));
        mx_lo = fmaxf(mx_lo, __shfl_xor_sync(0xffffffffu, mx_lo, 2));
        mx_hi = fmaxf(mx_hi, __shfl_xor_sync(0xffffffffu, mx_hi, 1));
        mx_hi = fmaxf(mx_hi, __shfl_xor_sync(0xffffffffu, mx_hi, 2));

        float mn_lo = fmaxf(m_lo, mx_lo), mn_hi = fmaxf(m_hi, mx_hi);
        float al_lo = __expf(m_lo - mn_lo), al_hi = __expf(m_hi - mn_hi);
        m_lo = mn_lo; m_hi = mn_hi;

        float rs_lo = 0.f, rs_hi = 0.f;
        uint32_t* plo = Ps + (wr + g) * PSTRIDE + 2 * tg;
        uint32_t* phi = Ps + (wr + g + 8) * PSTRIDE + 2 * tg;
#pragma unroll
        for (int ni = 0; ni < 8; ni++) {
            float p0 = __expf(sc[ni][0] - mn_lo);
            float p1 = __expf(sc[ni][1] - mn_lo);
            float p2 = __expf(sc[ni][2] - mn_hi);
            float p3 = __expf(sc[ni][3] - mn_hi);
            rs_lo += p0 + p1;
            rs_hi += p2 + p3;
            plo[ni * 8 + 0] = f2tf32(p0);
            plo[ni * 8 + 1] = f2tf32(p1);
            phi[ni * 8 + 0] = f2tf32(p2);
            phi[ni * 8 + 1] = f2tf32(p3);
        }
        rs_lo += __shfl_xor_sync(0xffffffffu, rs_lo, 1);
        rs_lo += __shfl_xor_sync(0xffffffffu, rs_lo, 2);
        rs_hi += __shfl_xor_sync(0xffffffffu, rs_hi, 1);
        rs_hi += __shfl_xor_sync(0xffffffffu, rs_hi, 2);
        l_lo = l_lo * al_lo + rs_lo;
        l_hi = l_hi * al_hi + rs_hi;

#pragma unroll
        for (int ni = 0; ni < 8; ni++) {
            o[ni][0] *= al_lo; o[ni][1] *= al_lo;
            o[ni][2] *= al_hi; o[ni][3] *= al_hi;
        }
        __syncwarp();

#pragma unroll
        for (int ki = 0; ki < 8; ki++) {
            uint32_t ap[4];
            ap[0] = Ps[(wr + g) * PSTRIDE + ki * 8 + tg];
            ap[1] = Ps[(wr + g + 8) * PSTRIDE + ki * 8 + tg];
            ap[2] = Ps[(wr + g) * PSTRIDE + ki * 8 + tg + 4];
            ap[3] = Ps[(wr + g + 8) * PSTRIDE + ki * 8 + tg + 4];
#pragma unroll
            for (int ni = 0; ni < 8; ni++) {
                uint32_t b0 = Vs[(ki * 8 + tg) * VSTRIDE + ni * 8 + g];
                uint32_t b1 = Vs[(ki * 8 + tg + 4) * VSTRIDE + ni * 8 + g];
                mma_tf32(o[ni], ap, b0, b1);
            }
        }
    }

    float inv_lo = 1.f / l_lo, inv_hi = 1.f / l_hi;
    int s = qs0 + wr + g;
    int cb = h * DH + 2 * tg;
    uint32_t* ctx = (uint32_t*)g_ctx;
#pragma unroll
    for (int ni = 0; ni < 8; ni++) {
        uint2 w0 = {f2tf32(o[ni][0] * inv_lo), f2tf32(o[ni][1] * inv_lo)};
        uint2 w1 = {f2tf32(o[ni][2] * inv_hi), f2tf32(o[ni][3] * inv_hi)};
        *(uint2*)&ctx[(size_t)(s * BB + b) * DMOD + cb + ni * 8] = w0;
        *(uint2*)&ctx[(size_t)((s + 8) * BB + b) * DMOD + cb + ni * 8] = w1;
    }
}

// ---------------- launch ----------------
extern "C" void kernel_launch(void* const* d_in, const int* in_sizes, int n_in,
                              void* d_out, int out_size)
{
    const float* Q  = (const float*)d_in[0];
    const float* Wq = (const float*)d_in[1];
    const float* bq = (const float*)d_in[2];
    const float* Wk = (const float*)d_in[3];
    const float* bk = (const float*)d_in[4];
    const float* Wv = (const float*)d_in[5];
    const float* bv = (const float*)d_in[6];
    const float* Wo = (const float*)d_in[7];
    const float* bo = (const float*)d_in[8];
    float* out = (float*)d_out;

    const int M = SS * BB;  // 8192

    // 1) pre-convert weights + input to tf32 bits (weights n-major)
    pack_qkv<<<(NQKV * DMOD + 255) / 256, 256>>>(Wq, bq, Wk, bk, Wv, bv);
    pack_wo<<<(DMOD * DMOD + 255) / 256, 256>>>(Wo);
    cvt_q<<<(M * DMOD / 4 + 255) / 256, 256>>>(Q);

    // 2) QKV projection: (8192x1024) @ (1024x3072) -> q/k/v (tf32 bits)
    {
        cudaFuncSetAttribute(tf32_gemm<1>, cudaFuncAttributeMaxDynamicSharedMemorySize,
                             GEMM_SMEM);
        dim3 grid(NQKV / BN, M / BM);
        tf32_gemm<1><<<grid, 256, GEMM_SMEM>>>(nullptr, nullptr);
    }

    // 3) causal flash attention -> g_ctx (tf32 bits)
    {
        size_t smem = (size_t)(64 * KSTRIDE + 64 * VSTRIDE + 128 * PSTRIDE) * 4;
        cudaFuncSetAttribute(flash_tf32, cudaFuncAttributeMaxDynamicSharedMemorySize,
                             (int)smem);
        flash_tf32<<<dim3(SS / 128, HH * BB), 256, smem>>>();
    }

    // 4) output projection: ctx (8192x1024) @ Wo + bo -> out (fp32)
    {
        cudaFuncSetAttribute(tf32_gemm<0>, cudaFuncAttributeMaxDynamicSharedMemorySize,
                             GEMM_SMEM);
        dim3 grid(DMOD / BN, M / BM);
        tf32_gemm<0><<<grid, 256, GEMM_SMEM>>>(bo, out);
    }
}

// round 12
// speedup vs baseline: 1.0029x; 1.0029x over previous
#include <cuda_runtime.h>
#include <math.h>
#include <stdint.h>

#define HH 16
#define BB 8
#define SS 1024
#define DMOD 1024
#define DH 64
#define NQKV 3072   // 16 heads * (64+64+64)

// ---------------- scratch (device globals; no allocation allowed) ----------------
__device__ uint32_t g_W[NQKV * DMOD];       // tf32 bits, n-major [n][k]
__device__ uint32_t g_Wo[DMOD * DMOD];      // tf32 bits, n-major [n][k]
__device__ uint32_t g_Atf[SS * BB * DMOD];  // tf32 bits of input Q, [m][k]
__device__ float g_bias[NQKV];
__device__ float g_q[HH * BB * SS * DH];    // tf32-valued floats [h][b][s][c]
__device__ float g_k[HH * BB * SS * DH];
__device__ float g_v[HH * BB * SS * DH];
__device__ float g_ctx[SS * BB * DMOD];     // tf32-valued floats [s][b][h*64+v]

// ---------------- helpers ----------------
__device__ __forceinline__ uint32_t f2tf32(float x) {
    uint32_t u;
    asm("cvt.rna.tf32.f32 %0, %1;" : "=r"(u) : "f"(x));
    return u;
}

__device__ __forceinline__ uint32_t smem_u32(const void* p) {
    uint32_t a;
    asm("{ .reg .u64 t; cvta.to.shared.u64 t, %1; cvt.u32.u64 %0, t; }"
        : "=r"(a) : "l"(p));
    return a;
}

__device__ __forceinline__ void cp16(uint32_t dst, const void* src) {
    asm volatile("cp.async.cg.shared.global [%0], [%1], 16;"
                 :: "r"(dst), "l"(src) : "memory");
}
#define CP_COMMIT() asm volatile("cp.async.commit_group;" ::: "memory")
#define CP_WAIT(n)  asm volatile("cp.async.wait_group %0;" :: "n"(n) : "memory")

__device__ __forceinline__ void mma_tf32(float* d, const uint32_t* a,
                                         uint32_t b0, uint32_t b1) {
    asm volatile(
        "mma.sync.aligned.m16n8k8.row.col.f32.tf32.tf32.f32 "
        "{%0,%1,%2,%3}, {%4,%5,%6,%7}, {%8,%9}, {%0,%1,%2,%3};"
        : "+f"(d[0]), "+f"(d[1]), "+f"(d[2]), "+f"(d[3])
        : "r"(a[0]), "r"(a[1]), "r"(a[2]), "r"(a[3]), "r"(b0), "r"(b1));
}

__device__ __forceinline__ void ldsm4(uint32_t* r, uint32_t addr) {
    asm volatile("ldmatrix.sync.aligned.m8n8.x4.shared.b16 {%0,%1,%2,%3}, [%4];"
                 : "=r"(r[0]), "=r"(r[1]), "=r"(r[2]), "=r"(r[3])
                 : "r"(addr));
}

// ---------------- pre-conversion kernels ----------------
__global__ void pack_qkv(const float* __restrict__ Wq, const float* __restrict__ bq,
                         const float* __restrict__ Wk, const float* __restrict__ bk,
                         const float* __restrict__ Wv, const float* __restrict__ bv)
{
    int idx = blockIdx.x * blockDim.x + threadIdx.x;
    if (idx >= NQKV * DMOD) return;
    int n = idx >> 10, d = idx & 1023;       // n-major [n][k]
    int h = n / 192, j = n % 192, t = j >> 6, c = j & 63;
    const float* Wsrc = (t == 0) ? Wq : (t == 1) ? Wk : Wv;
    g_W[idx] = f2tf32(Wsrc[(h * DMOD + d) * DH + c]);
    if (idx < NQKV) {
        int nn = idx;
        int h2 = nn / 192, j2 = nn % 192, t2 = j2 >> 6, c2 = j2 & 63;
        const float* bsrc = (t2 == 0) ? bq : (t2 == 1) ? bk : bv;
        g_bias[nn] = bsrc[h2 * DH + c2];
    }
}

__global__ void pack_wo(const float* __restrict__ Wo)
{
    int idx = blockIdx.x * blockDim.x + threadIdx.x;
    if (idx >= DMOD * DMOD) return;
    int k = idx >> 10, n = idx & 1023;       // coalesced read
    g_Wo[n * DMOD + k] = f2tf32(Wo[idx]);    // n-major write
}

__global__ void cvt_q(const float* __restrict__ Q)
{
    int idx = blockIdx.x * blockDim.x + threadIdx.x;   // float4 granularity
    float4 v = *(const float4*)(Q + idx * 4);
    uint4 u = {f2tf32(v.x), f2tf32(v.y), f2tf32(v.z), f2tf32(v.w)};
    *(uint4*)(g_Atf + idx * 4) = u;
}

// ---------------- TF32 tensor-core GEMM: cp.async + ldmatrix ----------------
// Block tile 128x128x32; 8 warps (2x4), warp tile 64x32 via 4x4 m16n8k8.
// A smem [m][BK] stride 36; B smem [n][BK] stride 36 (both ldmatrix-fed).
#define BM 128
#define BN 128
#define BK 32
#define STAGES 3
#define LSTRIDE 36
#define A_WORDS (BM * LSTRIDE)              // 4608
#define B_WORDS (BN * LSTRIDE)              // 4608
#define STG_WORDS (A_WORDS + B_WORDS)       // 9216
#define GEMM_SMEM (STAGES * STG_WORDS * 4)  // 110592 B

template <int MODE>
__global__ void __launch_bounds__(256, 2) tf32_gemm(const float* __restrict__ biasparam,
                                                    float* __restrict__ C)
{
    constexpr int N = (MODE == 1) ? NQKV : DMOD;
    constexpr int K = DMOD;
    extern __shared__ uint32_t smem[];

    const uint32_t* Ag = (MODE == 1) ? g_Atf : (const uint32_t*)g_ctx;
    const uint32_t* Bg = (MODE == 1) ? g_W   : g_Wo;

    int tid = threadIdx.x;
    int warp = tid >> 5, lane = tid & 31;
    int wm = warp >> 2, wn = warp & 3;
    int g = lane >> 2, tg = lane & 3;
    int rowBase = blockIdx.y * BM;
    int colBase = blockIdx.x * BN;

    uint32_t sbase = smem_u32(smem);

    // ldmatrix per-lane byte offsets
    // A x4 tiles: (m0-7,klo)(m8-15,klo)(m0-7,khi)(m8-15,khi)
    uint32_t aoff = ((((lane >> 3) & 1) * 8 + (lane & 7)) * LSTRIDE + (lane >> 4) * 4) * 4;
    // B x4 tiles: (n0-7,klo)(n0-7,khi)(n8-15,klo)(n8-15,khi)
    uint32_t boff = (((lane >> 4) * 8 + (lane & 7)) * LSTRIDE + ((lane >> 3) & 1) * 4) * 4;

    float acc[4][4][4];
#pragma unroll
    for (int mi = 0; mi < 4; mi++)
#pragma unroll
        for (int ni = 0; ni < 4; ni++)
#pragma unroll
            for (int r = 0; r < 4; r++) acc[mi][ni][r] = 0.f;

    const int ntiles = K / BK;   // 32

    auto load_stage = [&](int kt) {
        int st = kt % STAGES;
        uint32_t sa = sbase + st * STG_WORDS * 4;
        uint32_t sb = sa + A_WORDS * 4;
        int k0 = kt * BK;
#pragma unroll
        for (int i = 0; i < 4; i++) {
            int c = tid + 256 * i;
            int row = c >> 3, seg = c & 7;
            cp16(sa + (row * LSTRIDE + seg * 4) * 4,
                 Ag + (size_t)(rowBase + row) * K + k0 + seg * 4);
        }
#pragma unroll
        for (int i = 0; i < 4; i++) {
            int c = tid + 256 * i;
            int row = c >> 3, seg = c & 7;
            cp16(sb + (row * LSTRIDE + seg * 4) * 4,
                 Bg + (size_t)(colBase + row) * K + k0 + seg * 4);
        }
        CP_COMMIT();
    };

#pragma unroll
    for (int kt = 0; kt < STAGES - 1; kt++) load_stage(kt);

    for (int kt = 0; kt < ntiles; kt++) {
        CP_WAIT(STAGES - 2);
        __syncthreads();
        if (kt + STAGES - 1 < ntiles) load_stage(kt + STAGES - 1);
        else CP_COMMIT();

        int st = kt % STAGES;
        uint32_t asu = sbase + st * STG_WORDS * 4;
        uint32_t bsu = asu + A_WORDS * 4;

#pragma unroll
        for (int ks = 0; ks < 4; ks++) {
            uint32_t afrag[4][4], bfrag[4][2];
#pragma unroll
            for (int mi = 0; mi < 4; mi++)
                ldsm4(afrag[mi],
                      asu + (((wm * 64 + mi * 16) * LSTRIDE + ks * 8) * 4) + aoff);
#pragma unroll
            for (int np = 0; np < 2; np++) {
                uint32_t tmp[4];
                ldsm4(tmp, bsu + (((wn * 32 + np * 16) * LSTRIDE + ks * 8) * 4) + boff);
                bfrag[2 * np + 0][0] = tmp[0];
                bfrag[2 * np + 0][1] = tmp[1];
                bfrag[2 * np + 1][0] = tmp[2];
                bfrag[2 * np + 1][1] = tmp[3];
            }
#pragma unroll
            for (int mi = 0; mi < 4; mi++)
#pragma unroll
                for (int ni = 0; ni < 4; ni++)
                    mma_tf32(acc[mi][ni], afrag[mi], bfrag[ni][0], bfrag[ni][1]);
        }
    }

    // epilogue
#pragma unroll
    for (int mi = 0; mi < 4; mi++) {
#pragma unroll
        for (int ni = 0; ni < 4; ni++) {
            int r0 = rowBase + wm * 64 + mi * 16 + g;
            int cn = colBase + wn * 32 + ni * 8 + tg * 2;
            if (MODE == 0) {
                float2 bv = *(const float2*)&biasparam[cn];
                float2 o0 = {acc[mi][ni][0] + bv.x, acc[mi][ni][1] + bv.y};
                float2 o1 = {acc[mi][ni][2] + bv.x, acc[mi][ni][3] + bv.y};
                *(float2*)&C[(size_t)r0 * N + cn] = o0;
                *(float2*)&C[(size_t)(r0 + 8) * N + cn] = o1;
            } else {
#pragma unroll
                for (int e = 0; e < 4; e++) {
                    int r = r0 + (e >> 1) * 8;
                    int n = cn + (e & 1);
                    int s = r >> 3, b = r & 7;
                    int h = n / 192, jj = n % 192, ty = jj >> 6, c = jj & 63;
                    float val = acc[mi][ni][e] + g_bias[n];
                    float* bufp = (ty == 0) ? g_q : (ty == 1) ? g_k : g_v;
                    bufp[((h * BB + b) * SS + s) * DH + c] =
                        __uint_as_float(f2tf32(val));   // store tf32 bits
                }
            }
        }
    }
}

// ---------------- TF32 mma.sync flash attention (unchanged) ----------------
#define KSTRIDE 68
#define VSTRIDE 72
#define PSTRIDE 68

__global__ void __launch_bounds__(256) flash_tf32()
{
    extern __shared__ uint32_t sm[];
    uint32_t* Ks = sm;
    uint32_t* Vs = Ks + 64 * KSTRIDE;
    uint32_t* Ps = Vs + 64 * VSTRIDE;

    int tid = threadIdx.x;
    int warp = tid >> 5, lane = tid & 31;
    int g = lane >> 2, tg = lane & 3;
    int qx = blockIdx.x;
    int hb = blockIdx.y;
    int h = hb >> 3, b = hb & 7;
    int qs0 = qx * 128;
    int wr = warp * 16;

    const float* qg  = g_q + ((size_t)(h * BB + b) * SS + qs0) * DH;
    const uint32_t* kg0 = (const uint32_t*)g_k + (size_t)(h * BB + b) * SS * DH;
    const uint32_t* vg0 = (const uint32_t*)g_v + (size_t)(h * BB + b) * SS * DH;

    uint32_t aq[8][4];
#pragma unroll
    for (int ki = 0; ki < 8; ki++) {
        const float* qp = qg + (wr + g) * DH + ki * 8 + tg;
        aq[ki][0] = __float_as_uint(qp[0] * 0.125f);
        aq[ki][1] = __float_as_uint(qp[8 * DH] * 0.125f);
        aq[ki][2] = __float_as_uint(qp[4] * 0.125f);
        aq[ki][3] = __float_as_uint(qp[8 * DH + 4] * 0.125f);
    }

    float o[8][4];
#pragma unroll
    for (int ni = 0; ni < 8; ni++)
#pragma unroll
        for (int e = 0; e < 4; e++) o[ni][e] = 0.f;
    float m_lo = -INFINITY, m_hi = -INFINITY, l_lo = 0.f, l_hi = 0.f;

    const int nkt = 2 * (qx + 1);
    for (int kt = 0; kt < nkt; kt++) {
        const uint32_t* kg = kg0 + (size_t)kt * 64 * DH;
        const uint32_t* vg = vg0 + (size_t)kt * 64 * DH;
        __syncthreads();
#pragma unroll
        for (int t = 0; t < 4; t++) {
            int f = tid + t * 256;
            int row = f >> 4, c4 = (f & 15) << 2;
            uint4 kv = *(const uint4*)(kg + row * DH + c4);
            uint32_t* kp = Ks + row * KSTRIDE + c4;
            kp[0] = kv.x; kp[1] = kv.y; kp[2] = kv.z; kp[3] = kv.w;
            uint4 vv = *(const uint4*)(vg + row * DH + c4);
            uint32_t* vp = Vs + row * VSTRIDE + c4;
            vp[0] = vv.x; vp[1] = vv.y; vp[2] = vv.z; vp[3] = vv.w;
        }
        __syncthreads();

        float sc[8][4];
#pragma unroll
        for (int ni = 0; ni < 8; ni++)
#pragma unroll
            for (int e = 0; e < 4; e++) sc[ni][e] = 0.f;
#pragma unroll
        for (int ki = 0; ki < 8; ki++) {
#pragma unroll
            for (int ni = 0; ni < 8; ni++) {
                const uint32_t* kb = Ks + (ni * 8 + g) * KSTRIDE + ki * 8 + tg;
                mma_tf32(sc[ni], aq[ki], kb[0], kb[4]);
            }
        }

        if (kt * 64 + 63 > qs0 + wr) {
            int rlo = qs0 + wr + g, rhi = rlo + 8;
#pragma unroll
            for (int ni = 0; ni < 8; ni++) {
                int col = kt * 64 + ni * 8 + 2 * tg;
                if (col     > rlo) sc[ni][0] = -1e30f;
                if (col + 1 > rlo) sc[ni][1] = -1e30f;
                if (col     > rhi) sc[ni][2] = -1e30f;
                if (col + 1 > rhi) sc[ni][3] = -1e30f;
            }
        }

        float mx_lo = -1e30f, mx_hi = -1e30f;
#pragma unroll
        for (int ni = 0; ni < 8; ni++) {
            mx_lo = fmaxf(mx_lo, fmaxf(sc[ni][0], sc[ni][1]));
            mx_hi = fmaxf(mx_hi, fmaxf(sc[ni][2], sc[ni][3]));
        }
        mx_lo = fmaxf(mx_lo, __shfl_xor_sync(0xffffffffu, mx_lo, 1));
        mx_lo = fmaxf(mx_lo, __shfl_xor_sync(0xffffffffu, mx_lo, 2));
        mx_hi = fmaxf(mx_hi, __shfl_xor_sync(0xffffffffu, mx_hi, 1));
        mx_hi = fmaxf(mx_hi, __shfl_xor_sync(0xffffffffu, mx_hi, 2));

        float mn_lo = fmaxf(m_lo, mx_lo), mn_hi = fmaxf(m_hi, mx_hi);
        float al_lo = __expf(m_lo - mn_lo), al_hi = __expf(m_hi - mn_hi);
        m_lo = mn_lo; m_hi = mn_hi;

        float rs_lo = 0.f, rs_hi = 0.f;
        uint32_t* plo = Ps + (wr + g) * PSTRIDE + 2 * tg;
        uint32_t* phi = Ps + (wr + g + 8) * PSTRIDE + 2 * tg;
#pragma unroll
        for (int ni = 0; ni < 8; ni++) {
            float p0 = __expf(sc[ni][0] - mn_lo);
            float p1 = __expf(sc[ni][1] - mn_lo);
            float p2 = __expf(sc[ni][2] - mn_hi);
            float p3 = __expf(sc[ni][3] - mn_hi);
            rs_lo += p0 + p1;
            rs_hi += p2 + p3;
            plo[ni * 8 + 0] = f2tf32(p0);
            plo[ni * 8 + 1] = f2tf32(p1);
            phi[ni * 8 + 0] = f2tf32(p2);
            phi[ni * 8 + 1] = f2tf32(p3);
        }
        rs_lo += __shfl_xor_sync(0xffffffffu, rs_lo, 1);
        rs_lo += __shfl_xor_sync(0xffffffffu, rs_lo, 2);
        rs_hi += __shfl_xor_sync(0xffffffffu, rs_hi, 1);
        rs_hi += __shfl_xor_sync(0xffffffffu, rs_hi, 2);
        l_lo = l_lo * al_lo + rs_lo;
        l_hi = l_hi * al_hi + rs_hi;

#pragma unroll
        for (int ni = 0; ni < 8; ni++) {
            o[ni][0] *= al_lo; o[ni][1] *= al_lo;
            o[ni][2] *= al_hi; o[ni][3] *= al_hi;
        }
        __syncwarp();

#pragma unroll
        for (int ki = 0; ki < 8; ki++) {
            uint32_t ap[4];
            ap[0] = Ps[(wr + g) * PSTRIDE + ki * 8 + tg];
            ap[1] = Ps[(wr + g + 8) * PSTRIDE + ki * 8 + tg];
            ap[2] = Ps[(wr + g) * PSTRIDE + ki * 8 + tg + 4];
            ap[3] = Ps[(wr + g + 8) * PSTRIDE + ki * 8 + tg + 4];
#pragma unroll
            for (int ni = 0; ni < 8; ni++) {
                uint32_t b0 = Vs[(ki * 8 + tg) * VSTRIDE + ni * 8 + g];
                uint32_t b1 = Vs[(ki * 8 + tg + 4) * VSTRIDE + ni * 8 + g];
                mma_tf32(o[ni], ap, b0, b1);
            }
        }
    }

    float inv_lo = 1.f / l_lo, inv_hi = 1.f / l_hi;
    int s = qs0 + wr + g;
    int cb = h * DH + 2 * tg;
    uint32_t* ctx = (uint32_t*)g_ctx;
#pragma unroll
    for (int ni = 0; ni < 8; ni++) {
        uint2 w0 = {f2tf32(o[ni][0] * inv_lo), f2tf32(o[ni][1] * inv_lo)};
        uint2 w1 = {f2tf32(o[ni][2] * inv_hi), f2tf32(o[ni][3] * inv_hi)};
        *(uint2*)&ctx[(size_t)(s * BB + b) * DMOD + cb + ni * 8] = w0;
        *(uint2*)&ctx[(size_t)((s + 8) * BB + b) * DMOD + cb + ni * 8] = w1;
    }
}

// ---------------- launch ----------------
extern "C" void kernel_launch(void* const* d_in, const int* in_sizes, int n_in,
                              void* d_out, int out_size)
{
    const float* Q  = (const float*)d_in[0];
    const float* Wq = (const float*)d_in[1];
    const float* bq = (const float*)d_in[2];
    const float* Wk = (const float*)d_in[3];
    const float* bk = (const float*)d_in[4];
    const float* Wv = (const float*)d_in[5];
    const float* bv = (const float*)d_in[6];
    const float* Wo = (const float*)d_in[7];
    const float* bo = (const float*)d_in[8];
    float* out = (float*)d_out;

    const int M = SS * BB;  // 8192

    // 1) pre-convert weights + input to tf32 bits (weights n-major)
    pack_qkv<<<(NQKV * DMOD + 255) / 256, 256>>>(Wq, bq, Wk, bk, Wv, bv);
    pack_wo<<<(DMOD * DMOD + 255) / 256, 256>>>(Wo);
    cvt_q<<<(M * DMOD / 4 + 255) / 256, 256>>>(Q);

    // 2) QKV projection: (8192x1024) @ (1024x3072) -> q/k/v (tf32 bits)
    {
        cudaFuncSetAttribute(tf32_gemm<1>, cudaFuncAttributeMaxDynamicSharedMemorySize,
                             GEMM_SMEM);
        dim3 grid(NQKV / BN, M / BM);
        tf32_gemm<1><<<grid, 256, GEMM_SMEM>>>(nullptr, nullptr);
    }

    // 3) causal flash attention -> g_ctx (tf32 bits)
    {
        size_t smem = (size_t)(64 * KSTRIDE + 64 * VSTRIDE + 128 * PSTRIDE) * 4;
        cudaFuncSetAttribute(flash_tf32, cudaFuncAttributeMaxDynamicSharedMemorySize,
                             (int)smem);
        flash_tf32<<<dim3(SS / 128, HH * BB), 256, smem>>>();
    }

    // 4) output projection: ctx (8192x1024) @ Wo + bo -> out (fp32)
    {
        cudaFuncSetAttribute(tf32_gemm<0>, cudaFuncAttributeMaxDynamicSharedMemorySize,
                             GEMM_SMEM);
        dim3 grid(DMOD / BN, M / BM);
        tf32_gemm<0><<<grid, 256, GEMM_SMEM>>>(bo, out);
    }
}